// round 2
// baseline (speedup 1.0000x reference)
#include <cuda_runtime.h>
#include <cuda_bf16.h>
#include <cstdint>

// Problem constants (fixed by the dataset)
#define B_    4096
#define DACT  768
#define DHID  24576
#define K_    32

// ---------------------------------------------------------------------------
// Scratch (static __device__ arrays: allocation-free per harness rules)
// ---------------------------------------------------------------------------
__device__ int   g_tk_idx[B_ * K_];
__device__ float g_tk_val[B_ * K_];
// Fallback acts buffer in case the output layout is recon-only
__device__ float g_acts_scratch[(long)B_ * DHID];

// ---------------------------------------------------------------------------
// TF32 helpers
// ---------------------------------------------------------------------------
__device__ __forceinline__ float tf32_rna(float x) {
    uint32_t u;
    asm("cvt.rna.tf32.f32 %0, %1;" : "=r"(u) : "f"(x));
    return __uint_as_float(u);
}

__device__ __forceinline__ void mma_m16n8k8_tf32(float c[4], const float a[4], const float b[2]) {
    const uint32_t* A = reinterpret_cast<const uint32_t*>(a);
    const uint32_t* Bp = reinterpret_cast<const uint32_t*>(b);
    asm volatile(
        "mma.sync.aligned.m16n8k8.row.col.f32.tf32.tf32.f32 "
        "{%0,%1,%2,%3}, {%4,%5,%6,%7}, {%8,%9}, {%0,%1,%2,%3};\n"
        : "+f"(c[0]), "+f"(c[1]), "+f"(c[2]), "+f"(c[3])
        : "r"(A[0]), "r"(A[1]), "r"(A[2]), "r"(A[3]), "r"(Bp[0]), "r"(Bp[1]));
}

// ---------------------------------------------------------------------------
// Encode GEMM: acts = (A - b_pre) @ W_enc with 3xTF32 + hierarchical fp32
// accumulation (group flushed into acc every 32 k-values) for low noise.
// Block tile 128x128, BK=16, 256 threads (8 warps, 2x4 warp grid, 64x32/warp)
// ---------------------------------------------------------------------------
#define BM 128
#define BN 128
#define BK 16

__global__ void __launch_bounds__(256)
encode_gemm(const float* __restrict__ A, const float* __restrict__ W,
            const float* __restrict__ bpre, float* __restrict__ acts_out_opt)
{
    float* acts_out = acts_out_opt ? acts_out_opt : g_acts_scratch;

    __shared__ float As[2][BM][17];   // [hi/lo][row][k]
    __shared__ float Ws[2][BK][132];  // [hi/lo][k][col]

    const int tid  = threadIdx.x;
    const int warp = tid >> 5;
    const int lane = tid & 31;
    const int wm = warp >> 2;   // 0..1  (64 rows each)
    const int wn = warp & 3;    // 0..3  (32 cols each)
    const int lr = lane >> 2;   // 0..7
    const int lc = lane & 3;    // 0..3

    const int bm = blockIdx.y * BM;
    const int bn = blockIdx.x * BN;

    float acc[4][4][4];    // final accumulator
    float grp[4][4][4];    // short-horizon group accumulator (flushed often)
    #pragma unroll
    for (int mi = 0; mi < 4; ++mi)
        #pragma unroll
        for (int ni = 0; ni < 4; ++ni)
            #pragma unroll
            for (int q = 0; q < 4; ++q) { acc[mi][ni][q] = 0.f; grp[mi][ni][q] = 0.f; }

    const int NT = DACT / BK;   // 48 k-tiles
    for (int t = 0; t < NT; ++t) {
        const int k0 = t * BK;
        // ---- load A tile (128x16), subtract b_pre, split hi/lo ----
        #pragma unroll
        for (int p = 0; p < 2; ++p) {
            int i  = tid + p * 256;
            int r  = i >> 2;            // 0..127
            int c4 = (i & 3) << 2;      // 0,4,8,12
            const float4 av = *reinterpret_cast<const float4*>(A + (long)(bm + r) * DACT + k0 + c4);
            const float4 bv = *reinterpret_cast<const float4*>(bpre + k0 + c4);
            float v[4] = {av.x - bv.x, av.y - bv.y, av.z - bv.z, av.w - bv.w};
            #pragma unroll
            for (int j = 0; j < 4; ++j) {
                float hi = tf32_rna(v[j]);
                As[0][r][c4 + j] = hi;
                As[1][r][c4 + j] = tf32_rna(v[j] - hi);
            }
        }
        // ---- load W tile (16x128), split hi/lo ----
        #pragma unroll
        for (int p = 0; p < 2; ++p) {
            int i  = tid + p * 256;
            int r  = i >> 5;            // 0..15
            int c4 = (i & 31) << 2;     // 0..124
            const float4 wv = *reinterpret_cast<const float4*>(W + (long)(k0 + r) * DHID + bn + c4);
            float v[4] = {wv.x, wv.y, wv.z, wv.w};
            #pragma unroll
            for (int j = 0; j < 4; ++j) {
                float hi = tf32_rna(v[j]);
                Ws[0][r][c4 + j] = hi;
                Ws[1][r][c4 + j] = tf32_rna(v[j] - hi);
            }
        }
        __syncthreads();

        // ---- compute: two k-groups of 8, 3xTF32 into grp ----
        #pragma unroll
        for (int kk = 0; kk < 2; ++kk) {
            const int kb = kk * 8;
            float ah[4][4], al[4][4], bh[4][2], bl[4][2];
            #pragma unroll
            for (int mi = 0; mi < 4; ++mi) {
                int r0 = wm * 64 + mi * 16 + lr;
                ah[mi][0] = As[0][r0][kb + lc];
                ah[mi][1] = As[0][r0 + 8][kb + lc];
                ah[mi][2] = As[0][r0][kb + lc + 4];
                ah[mi][3] = As[0][r0 + 8][kb + lc + 4];
                al[mi][0] = As[1][r0][kb + lc];
                al[mi][1] = As[1][r0 + 8][kb + lc];
                al[mi][2] = As[1][r0][kb + lc + 4];
                al[mi][3] = As[1][r0 + 8][kb + lc + 4];
            }
            #pragma unroll
            for (int ni = 0; ni < 4; ++ni) {
                int cB = wn * 32 + ni * 8 + lr;
                bh[ni][0] = Ws[0][kb + lc][cB];
                bh[ni][1] = Ws[0][kb + lc + 4][cB];
                bl[ni][0] = Ws[1][kb + lc][cB];
                bl[ni][1] = Ws[1][kb + lc + 4][cB];
            }
            #pragma unroll
            for (int mi = 0; mi < 4; ++mi)
                #pragma unroll
                for (int ni = 0; ni < 4; ++ni) {
                    mma_m16n8k8_tf32(grp[mi][ni], ah[mi], bh[ni]);  // hi*hi
                    mma_m16n8k8_tf32(grp[mi][ni], ah[mi], bl[ni]);  // hi*lo
                    mma_m16n8k8_tf32(grp[mi][ni], al[mi], bh[ni]);  // lo*hi
                }
        }
        __syncthreads();

        // ---- flush group accumulator every 2 tiles (32 k-values) ----
        if (t & 1) {
            #pragma unroll
            for (int mi = 0; mi < 4; ++mi)
                #pragma unroll
                for (int ni = 0; ni < 4; ++ni)
                    #pragma unroll
                    for (int q = 0; q < 4; ++q) {
                        acc[mi][ni][q] += grp[mi][ni][q];
                        grp[mi][ni][q] = 0.f;
                    }
        }
    }

    // ---- epilogue ----
    #pragma unroll
    for (int mi = 0; mi < 4; ++mi) {
        #pragma unroll
        for (int ni = 0; ni < 4; ++ni) {
            int r0 = bm + wm * 64 + mi * 16 + lr;
            int c0 = bn + wn * 32 + ni * 8 + 2 * lc;
            float2 v01 = make_float2(acc[mi][ni][0], acc[mi][ni][1]);
            float2 v23 = make_float2(acc[mi][ni][2], acc[mi][ni][3]);
            *reinterpret_cast<float2*>(acts_out + (long)r0 * DHID + c0) = v01;
            *reinterpret_cast<float2*>(acts_out + (long)(r0 + 8) * DHID + c0) = v23;
        }
    }
}

// ---------------------------------------------------------------------------
// Top-K per row. One block (128 threads) per row. Each thread keeps an exact
// sorted top-32 of its 192-element strided slice in smem, then 32 rounds of
// block argmax merge. Tie-break: larger value first; on exact value ties the
// LOWER global index wins (matches jax's stable descending sort).
// ---------------------------------------------------------------------------
#define TT 128

__device__ __forceinline__ unsigned fkey(float v) {
    unsigned u = __float_as_uint(v);
    return (u & 0x80000000u) ? ~u : (u | 0x80000000u);
}

__global__ void __launch_bounds__(TT)
topk_kernel(const float* __restrict__ acts_opt, float* __restrict__ z_opt)
{
    const float* acts = acts_opt ? acts_opt : g_acts_scratch;
    const int row = blockIdx.x;
    const int t = threadIdx.x;
    const int wid = t >> 5, lane = t & 31;

    __shared__ float sv[K_ * TT];
    __shared__ int   si[K_ * TT];
    __shared__ unsigned long long red[5];

    const float* a = acts + (long)row * DHID;

    int cnt = 0;
    float vmin = 0.f;
    for (int c = t; c < DHID; c += TT) {
        float v = a[c];
        if (cnt == K_) {
            if (v <= vmin) continue;
            int j = K_ - 1;
            while (j > 0 && sv[(j - 1) * TT + t] < v) {
                sv[j * TT + t] = sv[(j - 1) * TT + t];
                si[j * TT + t] = si[(j - 1) * TT + t];
                --j;
            }
            sv[j * TT + t] = v; si[j * TT + t] = c;
            vmin = sv[(K_ - 1) * TT + t];
        } else {
            int j = cnt;
            while (j > 0 && sv[(j - 1) * TT + t] < v) {
                sv[j * TT + t] = sv[(j - 1) * TT + t];
                si[j * TT + t] = si[(j - 1) * TT + t];
                --j;
            }
            sv[j * TT + t] = v; si[j * TT + t] = c;
            ++cnt;
            if (cnt == K_) vmin = sv[(K_ - 1) * TT + t];
        }
    }
    for (int i = cnt; i < K_; ++i) sv[i * TT + t] = -__int_as_float(0x7f800000); // -inf pad
    __syncthreads();

    int head = 0;
    for (int r = 0; r < K_; ++r) {
        // pack: (value key << 32) | (DHID - idx)  -> max picks larger value,
        // and on exact value tie the SMALLER index (jax-stable).
        unsigned long long pk = 0ull;
        if (head < K_) {
            float v = sv[head * TT + t];
            int idx = si[head * TT + t];
            pk = ((unsigned long long)fkey(v) << 32) | (unsigned)(DHID - idx);
        }
        unsigned long long wk = pk;
        #pragma unroll
        for (int o = 16; o; o >>= 1) {
            unsigned long long q = __shfl_xor_sync(0xffffffffu, wk, o);
            if (q > wk) wk = q;
        }
        if (lane == 0) red[wid] = wk;
        __syncthreads();
        if (t == 0) {
            unsigned long long m = red[0];
            #pragma unroll
            for (int i = 1; i < 4; ++i) if (red[i] > m) m = red[i];
            red[4] = m;
        }
        __syncthreads();
        unsigned long long m = red[4];
        if (pk == m && pk != 0ull) {   // unique winner (pk embeds unique idx)
            float val = sv[head * TT + t];
            int   idx = si[head * TT + t];
            ++head;
            g_tk_val[row * K_ + r] = val;
            g_tk_idx[row * K_ + r] = idx;
            if (z_opt) z_opt[(long)row * DHID + idx] = val;
        }
        __syncthreads();
    }
}

// ---------------------------------------------------------------------------
// Decode: out[row] = b_pre + sum_j val_j * W_dec[idx_j, :]
// ---------------------------------------------------------------------------
__global__ void __launch_bounds__(256)
decode_kernel(const float* __restrict__ Wd, const float* __restrict__ bpre,
              float* __restrict__ out)
{
    const int row = blockIdx.x;
    __shared__ float sval[K_];
    __shared__ int   sidx[K_];
    if (threadIdx.x < K_) {
        sval[threadIdx.x] = g_tk_val[row * K_ + threadIdx.x];
        sidx[threadIdx.x] = g_tk_idx[row * K_ + threadIdx.x];
    }
    __syncthreads();
    for (int c = threadIdx.x; c < DACT; c += 256) {
        float acc = bpre[c];
        #pragma unroll
        for (int j = 0; j < K_; ++j)
            acc = fmaf(sval[j], Wd[(long)sidx[j] * DACT + c], acc);
        out[(long)row * DACT + c] = acc;
    }
}

// ---------------------------------------------------------------------------
// Launch: output layout assumed (A_reconstruct, acts, z) concatenated fp32.
// ---------------------------------------------------------------------------
extern "C" void kernel_launch(void* const* d_in, const int* in_sizes, int n_in,
                              void* d_out, int out_size)
{
    const float* A     = (const float*)d_in[0];
    const float* W_enc = (const float*)d_in[1];
    const float* W_dec = (const float*)d_in[2];
    const float* b_pre = (const float*)d_in[3];
    float* out = (float*)d_out;

    const long nRecon = (long)B_ * DACT;
    const long nActs  = (long)B_ * DHID;
    const bool full   = ((long)out_size >= nRecon + 2 * nActs);

    float* recon = out;
    float* acts  = full ? out + nRecon : nullptr;
    float* z     = full ? out + nRecon + nActs : nullptr;

    if (z) cudaMemsetAsync(z, 0, nActs * sizeof(float), 0);

    dim3 grid(DHID / BN, B_ / BM);
    encode_gemm<<<grid, 256>>>(A, W_enc, b_pre, acts);
    topk_kernel<<<B_, TT>>>(acts, z);
    decode_kernel<<<B_, 256>>>(W_dec, b_pre, recon);
}

// round 3
// speedup vs baseline: 1.2085x; 1.2085x over previous
#include <cuda_runtime.h>
#include <cuda_bf16.h>
#include <cstdint>

// Problem constants (fixed by the dataset)
#define B_    4096
#define DACT  768
#define DHID  24576
#define K_    32

// ---------------------------------------------------------------------------
// Scratch (static __device__ arrays: allocation-free per harness rules)
// ---------------------------------------------------------------------------
__device__ float g_Aprime[(long)B_ * DACT];           // A - b_pre
__device__ float g_acts_scratch[(long)B_ * DHID];     // fallback acts buffer

// ---------------------------------------------------------------------------
// TF32 helpers
// ---------------------------------------------------------------------------
__device__ __forceinline__ float tf32_rna(float x) {
    uint32_t u;
    asm("cvt.rna.tf32.f32 %0, %1;" : "=r"(u) : "f"(x));
    return __uint_as_float(u);
}

__device__ __forceinline__ void mma_m16n8k8_tf32(float c[4], const float a[4], const float b[2]) {
    const uint32_t* A = reinterpret_cast<const uint32_t*>(a);
    const uint32_t* Bp = reinterpret_cast<const uint32_t*>(b);
    asm volatile(
        "mma.sync.aligned.m16n8k8.row.col.f32.tf32.tf32.f32 "
        "{%0,%1,%2,%3}, {%4,%5,%6,%7}, {%8,%9}, {%0,%1,%2,%3};\n"
        : "+f"(c[0]), "+f"(c[1]), "+f"(c[2]), "+f"(c[3])
        : "r"(A[0]), "r"(A[1]), "r"(A[2]), "r"(A[3]), "r"(Bp[0]), "r"(Bp[1]));
}

// ---------------------------------------------------------------------------
// Pre-subtract: A' = A - b_pre (bit-identical to the subtraction previously
// done inside the GEMM tile loader)
// ---------------------------------------------------------------------------
__global__ void __launch_bounds__(256)
presub_kernel(const float* __restrict__ A, const float* __restrict__ bpre,
              float* __restrict__ Ap)
{
    const int i = blockIdx.x * 256 + threadIdx.x;       // float4 index
    const int col4 = i % (DACT / 4);
    const float4 a = reinterpret_cast<const float4*>(A)[i];
    const float4 b = reinterpret_cast<const float4*>(bpre)[col4];
    float4 r;
    r.x = a.x - b.x; r.y = a.y - b.y; r.z = a.z - b.z; r.w = a.w - b.w;
    reinterpret_cast<float4*>(Ap)[i] = r;
}

// ---------------------------------------------------------------------------
// Encode GEMM: acts = A' @ W_enc with 3xTF32 + hierarchical fp32 accumulation
// (flush every 32 k). Raw f32 smem tiles, double-buffered software pipeline,
// hi/lo split at fragment-load time (bit-identical to Round 2 numerics).
// Block tile 128x128, BK=16, 256 threads (8 warps, 2x4 warp grid, 64x32/warp)
// ---------------------------------------------------------------------------
#define BM 128
#define BN 128
#define BK 16

__global__ void __launch_bounds__(256)
encode_gemm(const float* __restrict__ Ap, const float* __restrict__ W,
            float* __restrict__ acts_out_opt)
{
    float* acts_out = acts_out_opt ? acts_out_opt : g_acts_scratch;

    __shared__ float As[2][BM][17];   // raw A' tiles, conflict-free frag loads
    __shared__ float Ws[2][BK][132];  // raw W tiles

    const int tid  = threadIdx.x;
    const int warp = tid >> 5;
    const int lane = tid & 31;
    const int wm = warp >> 2;   // 0..1  (64 rows each)
    const int wn = warp & 3;    // 0..3  (32 cols each)
    const int lr = lane >> 2;   // 0..7
    const int lc = lane & 3;    // 0..3

    const int bm = blockIdx.y * BM;
    const int bn = blockIdx.x * BN;

    // per-thread staging: A tile 2048 floats / 256 thr = 2 float4; same for W
    const int ar_r [2] = { (tid + 0)   >> 2, (tid + 256) >> 2 };
    const int ar_c4[2] = { ((tid + 0)  & 3) << 2, ((tid + 256) & 3) << 2 };
    const int wr_r [2] = { (tid + 0)   >> 5, (tid + 256) >> 5 };
    const int wr_c4[2] = { ((tid + 0)  & 31) << 2, ((tid + 256) & 31) << 2 };

    float acc[4][4][4];    // final accumulator
    float grp[4][4][4];    // short-horizon group accumulator
    #pragma unroll
    for (int mi = 0; mi < 4; ++mi)
        #pragma unroll
        for (int ni = 0; ni < 4; ++ni)
            #pragma unroll
            for (int q = 0; q < 4; ++q) { acc[mi][ni][q] = 0.f; grp[mi][ni][q] = 0.f; }

    float4 ra[2], rw[2];

    auto load_tiles = [&](int k0) {
        #pragma unroll
        for (int p = 0; p < 2; ++p) {
            ra[p] = *reinterpret_cast<const float4*>(Ap + (long)(bm + ar_r[p]) * DACT + k0 + ar_c4[p]);
            rw[p] = *reinterpret_cast<const float4*>(W  + (long)(k0 + wr_r[p]) * DHID + bn + wr_c4[p]);
        }
    };
    auto store_tiles = [&](int buf) {
        #pragma unroll
        for (int p = 0; p < 2; ++p) {
            As[buf][ar_r[p]][ar_c4[p] + 0] = ra[p].x;
            As[buf][ar_r[p]][ar_c4[p] + 1] = ra[p].y;
            As[buf][ar_r[p]][ar_c4[p] + 2] = ra[p].z;
            As[buf][ar_r[p]][ar_c4[p] + 3] = ra[p].w;
            Ws[buf][wr_r[p]][wr_c4[p] + 0] = rw[p].x;
            Ws[buf][wr_r[p]][wr_c4[p] + 1] = rw[p].y;
            Ws[buf][wr_r[p]][wr_c4[p] + 2] = rw[p].z;
            Ws[buf][wr_r[p]][wr_c4[p] + 3] = rw[p].w;
        }
    };

    // prologue
    load_tiles(0);
    store_tiles(0);
    __syncthreads();

    const int NT = DACT / BK;   // 48 k-tiles
    for (int t = 0; t < NT; ++t) {
        const int cur = t & 1;
        // issue next tile's global loads (overlap with compute below)
        if (t + 1 < NT) load_tiles((t + 1) * BK);

        // ---- compute: two k-groups of 8, 3xTF32 into grp ----
        #pragma unroll
        for (int kk = 0; kk < 2; ++kk) {
            const int kb = kk * 8;
            float ar4[4][4], ah[4][4], al[4][4];
            float br4[4][2], bh[4][2], bl[4][2];
            #pragma unroll
            for (int mi = 0; mi < 4; ++mi) {
                int r0 = wm * 64 + mi * 16 + lr;
                ar4[mi][0] = As[cur][r0][kb + lc];
                ar4[mi][1] = As[cur][r0 + 8][kb + lc];
                ar4[mi][2] = As[cur][r0][kb + lc + 4];
                ar4[mi][3] = As[cur][r0 + 8][kb + lc + 4];
                #pragma unroll
                for (int q = 0; q < 4; ++q) {
                    float hi = tf32_rna(ar4[mi][q]);
                    ah[mi][q] = hi;
                    al[mi][q] = tf32_rna(ar4[mi][q] - hi);
                }
            }
            #pragma unroll
            for (int ni = 0; ni < 4; ++ni) {
                int cB = wn * 32 + ni * 8 + lr;
                br4[ni][0] = Ws[cur][kb + lc][cB];
                br4[ni][1] = Ws[cur][kb + lc + 4][cB];
                #pragma unroll
                for (int q = 0; q < 2; ++q) {
                    float hi = tf32_rna(br4[ni][q]);
                    bh[ni][q] = hi;
                    bl[ni][q] = tf32_rna(br4[ni][q] - hi);
                }
            }
            #pragma unroll
            for (int mi = 0; mi < 4; ++mi)
                #pragma unroll
                for (int ni = 0; ni < 4; ++ni) {
                    mma_m16n8k8_tf32(grp[mi][ni], ah[mi], bh[ni]);  // hi*hi
                    mma_m16n8k8_tf32(grp[mi][ni], ah[mi], bl[ni]);  // hi*lo
                    mma_m16n8k8_tf32(grp[mi][ni], al[mi], bh[ni]);  // lo*hi
                }
        }

        // store next tile into the other buffer, then one sync per iteration
        if (t + 1 < NT) store_tiles(cur ^ 1);
        __syncthreads();

        // ---- flush group accumulator every 2 tiles (32 k-values) ----
        if (t & 1) {
            #pragma unroll
            for (int mi = 0; mi < 4; ++mi)
                #pragma unroll
                for (int ni = 0; ni < 4; ++ni)
                    #pragma unroll
                    for (int q = 0; q < 4; ++q) {
                        acc[mi][ni][q] += grp[mi][ni][q];
                        grp[mi][ni][q] = 0.f;
                    }
        }
    }

    // ---- epilogue ----
    #pragma unroll
    for (int mi = 0; mi < 4; ++mi) {
        #pragma unroll
        for (int ni = 0; ni < 4; ++ni) {
            int r0 = bm + wm * 64 + mi * 16 + lr;
            int c0 = bn + wn * 32 + ni * 8 + 2 * lc;
            float2 v01 = make_float2(acc[mi][ni][0], acc[mi][ni][1]);
            float2 v23 = make_float2(acc[mi][ni][2], acc[mi][ni][3]);
            *reinterpret_cast<float2*>(acts_out + (long)r0 * DHID + c0) = v01;
            *reinterpret_cast<float2*>(acts_out + (long)(r0 + 8) * DHID + c0) = v23;
        }
    }
}

// ---------------------------------------------------------------------------
// Fused Top-K + scatter + decode. One block (128 threads) per row.
// Phase 1: per-thread exact sorted top-32 lists (float4 scan).
// Phase 2: 32 rounds of block argmax (stable tie-break: lower index wins).
// Phase 3: decode recon[row] = b_pre + sum_j val_j * W_dec[idx_j, :]
// All phases exact / bit-identical in fp math to the unfused version.
// ---------------------------------------------------------------------------
#define TT 128

__device__ __forceinline__ unsigned fkey(float v) {
    unsigned u = __float_as_uint(v);
    return (u & 0x80000000u) ? ~u : (u | 0x80000000u);
}

__global__ void __launch_bounds__(TT)
topk_decode_kernel(const float* __restrict__ acts_opt, float* __restrict__ z_opt,
                   const float* __restrict__ Wd, const float* __restrict__ bpre,
                   float* __restrict__ recon)
{
    const float* acts = acts_opt ? acts_opt : g_acts_scratch;
    const int row = blockIdx.x;
    const int t = threadIdx.x;
    const int wid = t >> 5, lane = t & 31;

    __shared__ float sv[K_ * TT];
    __shared__ int   si[K_ * TT];
    __shared__ unsigned long long red[5];
    __shared__ float wval[K_];
    __shared__ int   widx[K_];

    const float* a = acts + (long)row * DHID;

    // ---- phase 1: per-thread sorted top-32 over a float4-strided slice ----
    int cnt = 0;
    float vmin = 0.f;
    for (int base = 0; base < DHID; base += TT * 4) {
        const int c0 = base + t * 4;
        const float4 v4 = *reinterpret_cast<const float4*>(a + c0);
        const float vs[4] = {v4.x, v4.y, v4.z, v4.w};
        #pragma unroll
        for (int q = 0; q < 4; ++q) {
            const float v = vs[q];
            const int c = c0 + q;
            if (cnt == K_) {
                if (v <= vmin) continue;
                int j = K_ - 1;
                while (j > 0 && sv[(j - 1) * TT + t] < v) {
                    sv[j * TT + t] = sv[(j - 1) * TT + t];
                    si[j * TT + t] = si[(j - 1) * TT + t];
                    --j;
                }
                sv[j * TT + t] = v; si[j * TT + t] = c;
                vmin = sv[(K_ - 1) * TT + t];
            } else {
                int j = cnt;
                while (j > 0 && sv[(j - 1) * TT + t] < v) {
                    sv[j * TT + t] = sv[(j - 1) * TT + t];
                    si[j * TT + t] = si[(j - 1) * TT + t];
                    --j;
                }
                sv[j * TT + t] = v; si[j * TT + t] = c;
                ++cnt;
                if (cnt == K_) vmin = sv[(K_ - 1) * TT + t];
            }
        }
    }
    for (int i = cnt; i < K_; ++i) sv[i * TT + t] = -__int_as_float(0x7f800000); // -inf
    __syncthreads();

    // ---- phase 2: 32 rounds of block argmax with stable tie-break ----
    int head = 0;
    for (int r = 0; r < K_; ++r) {
        unsigned long long pk = 0ull;
        if (head < K_) {
            float v = sv[head * TT + t];
            int idx = si[head * TT + t];
            pk = ((unsigned long long)fkey(v) << 32) | (unsigned)(DHID - idx);
        }
        unsigned long long wk = pk;
        #pragma unroll
        for (int o = 16; o; o >>= 1) {
            unsigned long long q = __shfl_xor_sync(0xffffffffu, wk, o);
            if (q > wk) wk = q;
        }
        if (lane == 0) red[wid] = wk;
        __syncthreads();
        if (t == 0) {
            unsigned long long m = red[0];
            #pragma unroll
            for (int i = 1; i < 4; ++i) if (red[i] > m) m = red[i];
            red[4] = m;
        }
        __syncthreads();
        if (pk == red[4] && pk != 0ull) {   // unique winner (pk embeds index)
            float val = sv[head * TT + t];
            int   idx = si[head * TT + t];
            ++head;
            wval[r] = val;
            widx[r] = idx;
            if (z_opt) z_opt[(long)row * DHID + idx] = val;
        }
        __syncthreads();
    }

    // ---- phase 3: decode ----
    for (int c = t; c < DACT; c += TT) {
        float acc = bpre[c];
        #pragma unroll
        for (int j = 0; j < K_; ++j)
            acc = fmaf(wval[j], Wd[(long)widx[j] * DACT + c], acc);
        recon[(long)row * DACT + c] = acc;
    }
}

// ---------------------------------------------------------------------------
// Launch: output layout (A_reconstruct, acts, z) concatenated fp32; falls
// back to recon-only if out_size is small.
// ---------------------------------------------------------------------------
extern "C" void kernel_launch(void* const* d_in, const int* in_sizes, int n_in,
                              void* d_out, int out_size)
{
    const float* A     = (const float*)d_in[0];
    const float* W_enc = (const float*)d_in[1];
    const float* W_dec = (const float*)d_in[2];
    const float* b_pre = (const float*)d_in[3];
    float* out = (float*)d_out;

    const long nRecon = (long)B_ * DACT;
    const long nActs  = (long)B_ * DHID;
    const bool full   = ((long)out_size >= nRecon + 2 * nActs);

    float* recon = out;
    float* acts  = full ? out + nRecon : nullptr;
    float* z     = full ? out + nRecon + nActs : nullptr;

    if (z) cudaMemsetAsync(z, 0, nActs * sizeof(float), 0);

    float* Ap = nullptr;
    cudaGetSymbolAddress((void**)&Ap, g_Aprime);

    presub_kernel<<<(B_ * DACT / 4) / 256, 256>>>(A, b_pre, Ap);

    dim3 grid(DHID / BN, B_ / BM);
    encode_gemm<<<grid, 256>>>(Ap, W_enc, acts);
    topk_decode_kernel<<<B_, TT>>>(acts, z, W_dec, b_pre, recon);
}

// round 4
// speedup vs baseline: 1.5779x; 1.3056x over previous
#include <cuda_runtime.h>
#include <cuda_bf16.h>
#include <cstdint>

// Problem constants (fixed by the dataset)
#define B_    4096
#define DACT  768
#define DHID  24576
#define K_    32

// ---------------------------------------------------------------------------
// Scratch (static __device__ arrays: allocation-free per harness rules)
// ---------------------------------------------------------------------------
__device__ float g_Aprime[(long)B_ * DACT];           // A - b_pre
__device__ float g_acts_scratch[(long)B_ * DHID];     // fallback acts buffer

// ---------------------------------------------------------------------------
// TF32 helpers
// ---------------------------------------------------------------------------
__device__ __forceinline__ float tf32_rna(float x) {
    uint32_t u;
    asm("cvt.rna.tf32.f32 %0, %1;" : "=r"(u) : "f"(x));
    return __uint_as_float(u);
}

__device__ __forceinline__ void mma_m16n8k8_tf32(float c[4], const float a[4], const float b[2]) {
    const uint32_t* A = reinterpret_cast<const uint32_t*>(a);
    const uint32_t* Bp = reinterpret_cast<const uint32_t*>(b);
    asm volatile(
        "mma.sync.aligned.m16n8k8.row.col.f32.tf32.tf32.f32 "
        "{%0,%1,%2,%3}, {%4,%5,%6,%7}, {%8,%9}, {%0,%1,%2,%3};\n"
        : "+f"(c[0]), "+f"(c[1]), "+f"(c[2]), "+f"(c[3])
        : "r"(A[0]), "r"(A[1]), "r"(A[2]), "r"(A[3]), "r"(Bp[0]), "r"(Bp[1]));
}

__device__ __forceinline__ void cp_async16(uint32_t dst_smem, const void* src) {
    asm volatile("cp.async.ca.shared.global [%0], [%1], 16;" :: "r"(dst_smem), "l"(src));
}
#define CP_COMMIT() asm volatile("cp.async.commit_group;")
#define CP_WAIT(n)  asm volatile("cp.async.wait_group %0;" :: "n"(n))

// ---------------------------------------------------------------------------
// Pre-subtract: A' = A - b_pre (bit-identical subtraction)
// ---------------------------------------------------------------------------
__global__ void __launch_bounds__(256)
presub_kernel(const float* __restrict__ A, const float* __restrict__ bpre,
              float* __restrict__ Ap)
{
    const int i = blockIdx.x * 256 + threadIdx.x;       // float4 index
    const int col4 = i % (DACT / 4);
    const float4 a = reinterpret_cast<const float4*>(A)[i];
    const float4 b = reinterpret_cast<const float4*>(bpre)[col4];
    float4 r;
    r.x = a.x - b.x; r.y = a.y - b.y; r.z = a.z - b.z; r.w = a.w - b.w;
    reinterpret_cast<float4*>(Ap)[i] = r;
}

// ---------------------------------------------------------------------------
// Encode GEMM: acts = A' @ W_enc, 3xTF32, hierarchical accumulation (flush
// every 32 k) — per-output fp sequence bit-identical to previous rounds.
// 512 threads, warp grid 4x4 (32x32/warp), cp.async 4-stage pipeline.
// ---------------------------------------------------------------------------
#define BM 128
#define BN 128
#define BK 16
#define STAGES 4
#define A_STRIDE 20     // floats per A row (16B-aligned, conflict-free frags)
#define W_STRIDE 132    // floats per W row
#define A_TILE_FL (BM * A_STRIDE)   // 2560
#define W_TILE_FL (BK * W_STRIDE)   // 2112
#define SMEM_FLOATS (STAGES * (A_TILE_FL + W_TILE_FL))  // 18688 -> 74752 B

__global__ void __launch_bounds__(512, 1)
encode_gemm(const float* __restrict__ Ap, const float* __restrict__ W,
            float* __restrict__ acts_out_opt)
{
    float* acts_out = acts_out_opt ? acts_out_opt : g_acts_scratch;

    extern __shared__ float smem[];
    float* sA = smem;                      // [STAGES][A_TILE_FL]
    float* sW = smem + STAGES * A_TILE_FL; // [STAGES][W_TILE_FL]
    const uint32_t sbase = (uint32_t)__cvta_generic_to_shared(smem);

    const int tid  = threadIdx.x;
    const int warp = tid >> 5;
    const int lane = tid & 31;
    const int wm = warp >> 2;   // 0..3  (32 rows each)
    const int wn = warp & 3;    // 0..3  (32 cols each)
    const int lr = lane >> 2;   // 0..7
    const int lc = lane & 3;    // 0..3

    const int bm = blockIdx.y * BM;
    const int bn = blockIdx.x * BN;

    // cp.async mapping: 512 chunks of 16B per tile, 1 per thread for A and W
    const int a_row = tid >> 2;            // 0..127
    const int a_c4  = (tid & 3) << 2;      // 0,4,8,12
    const int w_row = tid >> 5;            // 0..15
    const int w_c4  = (tid & 31) << 2;     // 0..124
    const float* a_src_base = Ap + (long)(bm + a_row) * DACT + a_c4;
    const float* w_src_base = W  + (long)w_row * DHID + bn + w_c4;

    auto issue_tile = [&](int t, int st) {
        const int k0 = t * BK;
        cp_async16(sbase + (st * A_TILE_FL + a_row * A_STRIDE + a_c4) * 4,
                   a_src_base + k0);
        cp_async16(sbase + (STAGES * A_TILE_FL + st * W_TILE_FL + w_row * W_STRIDE + w_c4) * 4,
                   w_src_base + (long)k0 * DHID);
    };

    float acc[2][4][4];
    float grp[2][4][4];
    #pragma unroll
    for (int mi = 0; mi < 2; ++mi)
        #pragma unroll
        for (int ni = 0; ni < 4; ++ni)
            #pragma unroll
            for (int q = 0; q < 4; ++q) { acc[mi][ni][q] = 0.f; grp[mi][ni][q] = 0.f; }

    const int NT = DACT / BK;   // 48

    // prologue: 3 tiles in flight
    issue_tile(0, 0); CP_COMMIT();
    issue_tile(1, 1); CP_COMMIT();
    issue_tile(2, 2); CP_COMMIT();

    for (int t = 0; t < NT; ++t) {
        const int st = t & (STAGES - 1);
        const int rem = NT - 1 - t;
        if (rem >= 2)      { CP_WAIT(2); }
        else if (rem == 1) { CP_WAIT(1); }
        else               { CP_WAIT(0); }
        __syncthreads();
        if (t + 3 < NT) { issue_tile(t + 3, (t + 3) & (STAGES - 1)); CP_COMMIT(); }

        const float* As = sA + st * A_TILE_FL;
        const float* Ws = sW + st * W_TILE_FL;

        #pragma unroll
        for (int kk = 0; kk < 2; ++kk) {
            const int kb = kk * 8;
            float ah[2][4], al[2][4], bh[4][2], bl[4][2];
            #pragma unroll
            for (int mi = 0; mi < 2; ++mi) {
                const int r0 = wm * 32 + mi * 16 + lr;
                float v0 = As[r0 * A_STRIDE + kb + lc];
                float v1 = As[(r0 + 8) * A_STRIDE + kb + lc];
                float v2 = As[r0 * A_STRIDE + kb + lc + 4];
                float v3 = As[(r0 + 8) * A_STRIDE + kb + lc + 4];
                float h;
                h = tf32_rna(v0); ah[mi][0] = h; al[mi][0] = tf32_rna(v0 - h);
                h = tf32_rna(v1); ah[mi][1] = h; al[mi][1] = tf32_rna(v1 - h);
                h = tf32_rna(v2); ah[mi][2] = h; al[mi][2] = tf32_rna(v2 - h);
                h = tf32_rna(v3); ah[mi][3] = h; al[mi][3] = tf32_rna(v3 - h);
            }
            #pragma unroll
            for (int ni = 0; ni < 4; ++ni) {
                const int cB = wn * 32 + ni * 8 + lr;
                float v0 = Ws[(kb + lc) * W_STRIDE + cB];
                float v1 = Ws[(kb + lc + 4) * W_STRIDE + cB];
                float h;
                h = tf32_rna(v0); bh[ni][0] = h; bl[ni][0] = tf32_rna(v0 - h);
                h = tf32_rna(v1); bh[ni][1] = h; bl[ni][1] = tf32_rna(v1 - h);
            }
            #pragma unroll
            for (int mi = 0; mi < 2; ++mi)
                #pragma unroll
                for (int ni = 0; ni < 4; ++ni) {
                    mma_m16n8k8_tf32(grp[mi][ni], ah[mi], bh[ni]);  // hi*hi
                    mma_m16n8k8_tf32(grp[mi][ni], ah[mi], bl[ni]);  // hi*lo
                    mma_m16n8k8_tf32(grp[mi][ni], al[mi], bh[ni]);  // lo*hi
                }
        }

        if (t & 1) {   // flush every 32 k (same cadence as before)
            #pragma unroll
            for (int mi = 0; mi < 2; ++mi)
                #pragma unroll
                for (int ni = 0; ni < 4; ++ni)
                    #pragma unroll
                    for (int q = 0; q < 4; ++q) {
                        acc[mi][ni][q] += grp[mi][ni][q];
                        grp[mi][ni][q] = 0.f;
                    }
        }
    }

    // epilogue
    #pragma unroll
    for (int mi = 0; mi < 2; ++mi) {
        #pragma unroll
        for (int ni = 0; ni < 4; ++ni) {
            const int r0 = bm + wm * 32 + mi * 16 + lr;
            const int c0 = bn + wn * 32 + ni * 8 + 2 * lc;
            float2 v01 = make_float2(acc[mi][ni][0], acc[mi][ni][1]);
            float2 v23 = make_float2(acc[mi][ni][2], acc[mi][ni][3]);
            *reinterpret_cast<float2*>(acts_out + (long)r0 * DHID + c0) = v01;
            *reinterpret_cast<float2*>(acts_out + (long)(r0 + 8) * DHID + c0) = v23;
        }
    }
}

// ---------------------------------------------------------------------------
// Fused exact Top-K (histogram select) + z scatter + decode. 1 block/row.
// Pass 1: 4096-bin histogram over monotone key. Find bin b* of the K-th value.
// Pass 2: bins > b* are winners outright; bin == b* resolved by warp argmax
// with (value desc, idx asc) stable tie-break. Then decode from smem winners.
// ---------------------------------------------------------------------------
#define TPT 256
#define NBIN 4096
#define MAXC 1024

__device__ __forceinline__ unsigned fkey(float v) {
    unsigned u = __float_as_uint(v);
    return (u & 0x80000000u) ? ~u : (u | 0x80000000u);
}

__global__ void __launch_bounds__(TPT)
topk_decode_kernel(const float* __restrict__ acts_opt, float* __restrict__ z_opt,
                   const float* __restrict__ Wd, const float* __restrict__ bpre,
                   float* __restrict__ recon)
{
    const float* acts = acts_opt ? acts_opt : g_acts_scratch;
    const int row = blockIdx.x;
    const int t = threadIdx.x;

    __shared__ unsigned hist[NBIN];
    __shared__ unsigned part[TPT];
    __shared__ float cval[MAXC];
    __shared__ int   cidx[MAXC];
    __shared__ float wv[K_];
    __shared__ int   wi[K_];
    __shared__ int   s_bstar, s_nhi, s_nwin, s_ncand;

    const float* a = acts + (long)row * DHID;

    // ---- pass 1: histogram ----
    #pragma unroll
    for (int i = 0; i < NBIN / TPT; ++i) hist[t + i * TPT] = 0;
    if (t == 0) { s_nwin = 0; s_ncand = 0; }
    __syncthreads();

    for (int c0 = t * 4; c0 < DHID; c0 += TPT * 4) {
        const float4 v4 = *reinterpret_cast<const float4*>(a + c0);
        atomicAdd(&hist[fkey(v4.x) >> 20], 1u);
        atomicAdd(&hist[fkey(v4.y) >> 20], 1u);
        atomicAdd(&hist[fkey(v4.z) >> 20], 1u);
        atomicAdd(&hist[fkey(v4.w) >> 20], 1u);
    }
    __syncthreads();

    // per-thread 16-bin partial sums, then thread0 finds threshold bin
    {
        unsigned s = 0;
        #pragma unroll
        for (int i = 0; i < 16; ++i) s += hist[t * 16 + i];
        part[t] = s;
    }
    __syncthreads();
    if (t == 0) {
        unsigned cum = 0;
        int seg = 0;
        for (int s = TPT - 1; s >= 0; --s) {
            if (cum + part[s] >= K_) { seg = s; break; }
            cum += part[s];
        }
        int bstar = seg * 16;
        for (int b = seg * 16 + 15; b >= seg * 16; --b) {
            if (cum + hist[b] >= K_) { bstar = b; break; }
            cum += hist[b];
        }
        s_bstar = bstar;
        s_nhi   = (int)cum;        // count strictly above bin bstar (< K)
    }
    __syncthreads();

    const int bstar = s_bstar;
    const int nhi   = s_nhi;

    // ---- pass 2: emit winners / boundary candidates ----
    for (int c0 = t * 4; c0 < DHID; c0 += TPT * 4) {
        const float4 v4 = *reinterpret_cast<const float4*>(a + c0);
        const float vs[4] = {v4.x, v4.y, v4.z, v4.w};
        #pragma unroll
        for (int q = 0; q < 4; ++q) {
            const float v = vs[q];
            const int bin = (int)(fkey(v) >> 20);
            if (bin > bstar) {
                int p = atomicAdd(&s_nwin, 1);
                wv[p] = v; wi[p] = c0 + q;
                if (z_opt) z_opt[(long)row * DHID + c0 + q] = v;
            } else if (bin == bstar) {
                int p = atomicAdd(&s_ncand, 1);
                if (p < MAXC) { cval[p] = v; cidx[p] = c0 + q; }
            }
        }
    }
    __syncthreads();

    // ---- resolve boundary bin with warp 0 (stable: value desc, idx asc) ----
    if (t < 32) {
        const int m = min(s_ncand, MAXC);
        const int need = K_ - nhi;
        const float NEGINF = __int_as_float(0xff800000);
        for (int r = 0; r < need; ++r) {
            unsigned long long best = 0ull; int bpos = -1;
            for (int j = t; j < m; j += 32) {
                float v = cval[j];
                unsigned long long k =
                    ((unsigned long long)fkey(v) << 32) | (unsigned)(DHID - cidx[j]);
                if (v != NEGINF && k > best) { best = k; bpos = j; }
            }
            unsigned long long wk = best;
            #pragma unroll
            for (int o = 16; o; o >>= 1) {
                unsigned long long q = __shfl_xor_sync(0xffffffffu, wk, o);
                if (q > wk) wk = q;
            }
            if (best == wk && bpos >= 0 && wk != 0ull) {
                // unique winner (key embeds unique index)
                int slot = nhi + r;
                wv[slot] = cval[bpos];
                wi[slot] = cidx[bpos];
                if (z_opt) z_opt[(long)row * DHID + cidx[bpos]] = cval[bpos];
                cval[bpos] = NEGINF;
            }
            __syncwarp();
        }
    }
    __syncthreads();

    // ---- decode: recon[row] = b_pre + sum_j wv[j] * W_dec[wi[j], :] ----
    for (int c = t; c < DACT; c += TPT) {
        float acc = bpre[c];
        #pragma unroll
        for (int j = 0; j < K_; ++j)
            acc = fmaf(wv[j], Wd[(long)wi[j] * DACT + c], acc);
        recon[(long)row * DACT + c] = acc;
    }
}

// ---------------------------------------------------------------------------
// Launch
// ---------------------------------------------------------------------------
extern "C" void kernel_launch(void* const* d_in, const int* in_sizes, int n_in,
                              void* d_out, int out_size)
{
    const float* A     = (const float*)d_in[0];
    const float* W_enc = (const float*)d_in[1];
    const float* W_dec = (const float*)d_in[2];
    const float* b_pre = (const float*)d_in[3];
    float* out = (float*)d_out;

    const long nRecon = (long)B_ * DACT;
    const long nActs  = (long)B_ * DHID;
    const bool full   = ((long)out_size >= nRecon + 2 * nActs);

    float* recon = out;
    float* acts  = full ? out + nRecon : nullptr;
    float* z     = full ? out + nRecon + nActs : nullptr;

    if (z) cudaMemsetAsync(z, 0, nActs * sizeof(float), 0);

    float* Ap = nullptr;
    cudaGetSymbolAddress((void**)&Ap, g_Aprime);

    presub_kernel<<<(B_ * DACT / 4) / 256, 256>>>(A, b_pre, Ap);

    const int smem_bytes = SMEM_FLOATS * 4;   // 74752
    static int attr_set = 0;
    if (!attr_set) {
        cudaFuncSetAttribute(encode_gemm,
                             cudaFuncAttributeMaxDynamicSharedMemorySize, smem_bytes);
        attr_set = 1;
    }
    dim3 grid(DHID / BN, B_ / BM);
    encode_gemm<<<grid, 512, smem_bytes>>>(Ap, W_enc, acts);

    topk_decode_kernel<<<B_, TPT>>>(acts, z, W_dec, b_pre, recon);
}